// round 16
// baseline (speedup 1.0000x reference)
#include <cuda_runtime.h>
#include <cuda_bf16.h>
#include <math.h>
#include <stdint.h>

// ---------------- problem constants ----------------
#define NWIN 200
#define WINL 160
#define HOPL 80
#define INPD 40
#define HID  768
#define NB   128
#define NT   512
#define NCT  224           // compute threads (7 warps)
#define NST  288           // staging threads (9 warps)

// smem layout (bytes)
#define OFF_BS   0                   // bias: 48 floats
#define OFF_A    1024                // A ring: 2 slots x (hi 14336 + lo 14336) = 57344
#define OFF_BL   58368               // Wlo ring: 2 slots x 6144
#define OFF_BH   70656               // Wh resident: 24 chunks x 48 rows x 128B = 147456
#define SMEM_TOT 218112

// named barrier ids (0 reserved for __syncthreads)
#define FULL0 1
#define FULL1 2
#define EMPT0 3
#define EMPT1 4
#define HDONE 5
#define GBARS 6

#define BAR_SYNC(id, cnt)   asm volatile("bar.sync %0, %1;"   :: "r"(id), "r"(cnt) : "memory")
#define BAR_ARRIVE(id, cnt) asm volatile("bar.arrive %0, %1;" :: "r"(id), "r"(cnt) : "memory")

// ---------------- persistent device scratch ----------------
__device__ uint32_t g_hPack[2][NWIN * HID];            // packed (lo16<<16 | hi16) bf16 pairs
__device__ uint32_t g_seqPack[2][NWIN * WINL * HID];   // layer0/1 output sequences
__device__ uint32_t g_xPack[NWIN * WINL * INPD + 64];  // windowed input, packed
__device__ __align__(16) __nv_bfloat16 g_wlo[NB * 24 * 3072];  // per-CTA pre-swizzled Wlo
__device__ float g_hF[NWIN * HID];                     // final-layer h (fp32)
__device__ float g_y[NWIN * 256];
__device__ unsigned g_barcnt = 0;
__device__ unsigned g_bargen = 0;

struct P {
    const float *x;
    const float *wih0, *whh0, *bih0, *bhh0;
    const float *wih1, *whh1, *bih1, *bhh1;
    const float *wih2, *whh2, *bih2, *bhh2;
};

// ---------------- helpers ----------------
__device__ __forceinline__ uint32_t smem_u32(const void* p) {
    uint32_t a;
    asm("{ .reg .u64 t; cvta.to.shared.u64 t, %1; cvt.u32.u64 %0, t; }" : "=r"(a) : "l"(p));
    return a;
}
__device__ __forceinline__ void grid_bar() {          // all-thread layer-level barrier
    __syncthreads();
    if (threadIdx.x == 0) {
        unsigned g = atomicAdd(&g_bargen, 0u);
        __threadfence();
        unsigned old = atomicAdd(&g_barcnt, 1u);
        if (old == gridDim.x - 1) {
            g_barcnt = 0;
            __threadfence();
            atomicAdd(&g_bargen, 1u);
        } else {
            while (atomicAdd(&g_bargen, 0u) == g) __nanosleep(64);
        }
        __threadfence();
    }
    __syncthreads();
}
__device__ __forceinline__ float sigf(float v) { return 1.f / (1.f + __expf(-v)); }
__device__ __forceinline__ float tanhfast(float x) {
    float ax = fabsf(x);
    float e = __expf(-2.f * ax);
    return copysignf((1.f - e) / (1.f + e), x);
}
__device__ __forceinline__ unsigned sw128(unsigned off) { return off ^ ((off >> 3) & 0x70); }
__device__ __forceinline__ uint32_t packf(float v) {
    __nv_bfloat16 h = __float2bfloat16(v);
    __nv_bfloat16 l = __float2bfloat16(v - __bfloat162float(h));
    return ((uint32_t)__bfloat16_as_ushort(l) << 16) | (uint32_t)__bfloat16_as_ushort(h);
}
__device__ __forceinline__ void mma16816(float* d, const uint32_t* a, const uint32_t* b) {
    asm volatile(
        "mma.sync.aligned.m16n8k16.row.col.f32.bf16.bf16.f32 "
        "{%0,%1,%2,%3}, {%4,%5,%6,%7}, {%8,%9}, {%0,%1,%2,%3};"
        : "+f"(d[0]), "+f"(d[1]), "+f"(d[2]), "+f"(d[3])
        : "r"(a[0]), "r"(a[1]), "r"(a[2]), "r"(a[3]), "r"(b[0]), "r"(b[1]));
}
__device__ __forceinline__ void ldsm4(uint32_t* r, uint32_t addr) {
    asm volatile("ldmatrix.sync.aligned.m8n8.x4.shared.b16 {%0,%1,%2,%3}, [%4];"
        : "=r"(r[0]), "=r"(r[1]), "=r"(r[2]), "=r"(r[3]) : "r"(addr));
}

// ============================================================
// Persistent kernel: full 3-layer, 160-step LSTM recurrence
// ============================================================
__global__ void __launch_bounds__(NT, 1) lstm_all(P p)
{
    extern __shared__ char smc[];
    const uint32_t sb = smem_u32(smc);
    float* b_s = (float*)(smc + OFF_BS);

    const int tid  = threadIdx.x;
    const int wid  = tid >> 5;
    const int lane = tid & 31;
    const int bid  = blockIdx.x;
    const int grp  = bid >> 6;               // rows grp*100 .. +99
    const int nb   = bid & 63;
    const int u0   = nb * 12;                // 12 hidden units owned
    const bool isC = (tid < NCT);            // compute warps 0-6
    const int stid = tid - NCT;              // staging thread id (valid if !isC)

    // compute-warp ldmatrix geometry (m-tile = wid; B spans all 48 cols)
    const int aRow = wid * 16 + (lane & 15);
    const uint32_t aSwz = (uint32_t)(aRow & 7) << 4;
    const uint32_t aBB  = (uint32_t)aRow * 128 + ((lane & 16) ? 16u : 0u);
    const uint32_t colRel = (uint32_t)((lane & 7) + ((lane & 16) ? 8 : 0));
    const uint32_t bSwzL  = (uint32_t)(lane & 7) << 4;
    const uint32_t bKofs  = (lane & 8) ? 16u : 0u;

    // zero the whole A ring once: pad rows (100..111) stay zero forever
    for (int i = tid * 16; i < 57344; i += NT * 16)
        *(uint4*)(smc + OFF_A + i) = make_uint4(0, 0, 0, 0);

    // precompute windowed, packed input (whole grid)
    for (int idx = bid * NT + tid; idx < NWIN * WINL * INPD; idx += NB * NT) {
        int m = idx / (WINL * INPD);
        int r2 = idx - m * WINL * INPD;
        int tt = r2 / INPD;
        int i = r2 - tt * INPD;
        g_xPack[idx] = packf(__ldcg(&p.x[(m * HOPL + tt) * INPD + i]));
    }
    grid_bar();

    const float* wihA[3] = { p.wih0, p.wih1, p.wih2 };
    const float* whhA[3] = { p.whh0, p.whh1, p.whh2 };
    const float* bihA[3] = { p.bih0, p.bih1, p.bih2 };
    const float* bhhA[3] = { p.bhh0, p.bhh1, p.bhh2 };

    unsigned cnt = 0;                         // chunk ring cursor (both groups track)

    for (int l = 0; l < 3; l++) {
        const int in_dim = (l == 0) ? INPD : HID;
        const int Ktot = HID + in_dim;
        const int nch = (Ktot + 63) >> 6;     // 13 or 24
        const uint32_t* xsrc = (l == 0) ? g_xPack : g_seqPack[l - 1];
        const long xrs = (l == 0) ? (long)WINL * INPD : (long)WINL * HID;
        const int xw = (l == 0) ? INPD : HID;
        uint32_t* seqOut = (l < 2) ? g_seqPack[l] : nullptr;
        const float* wih = wihA[l];
        const float* whh = whhA[l];

        // ---- weight prep (all threads): Wh hi -> smem resident, Wlo -> pre-swizzled global ----
        for (int idx = tid; idx < 48 * 1536; idx += NT) {
            int j = idx / 1536, k = idx - j * 1536;
            int u = j >> 2, g = j & 3;
            int col = g * HID + u0 + u;
            float v = 0.f;
            if (k < HID) v = whh[col * HID + k];
            else { int kk = k - HID; if (kk < in_dim) v = wih[col * in_dim + kk]; }
            __nv_bfloat16 hi = __float2bfloat16(v);
            __nv_bfloat16 lo = __float2bfloat16(v - __bfloat162float(hi));
            int ch = k >> 6, kk2 = k & 63;
            unsigned sw = sw128((unsigned)(j * 128 + kk2 * 2));
            *(__nv_bfloat16*)(smc + OFF_BH + ch * 6144 + sw) = hi;
            g_wlo[(size_t)(bid * 24 + ch) * 3072 + (sw >> 1)] = lo;
        }
        if (tid < 48) {
            int u = tid >> 2, g = tid & 3;
            int col = g * HID + u0 + u;
            b_s[tid] = bihA[l][col] + bhhA[l][col];
        }
        for (int i = tid; i < 1200; i += NT) g_hPack[0][bid * 1200 + i] = 0u;
        grid_bar();

        if (!isC) {
            // =============== PRODUCER warps (9): stage A + Wlo chunks ===============
            for (int t = 0; t < WINL; t++) {
                if (t > 0) {
                    BAR_SYNC(HDONE, NT);                 // wait local epilogue of t-1
                    if (stid == 0) {                     // inter-CTA h barrier
                        unsigned g = atomicAdd(&g_bargen, 0u);
                        __threadfence();
                        unsigned old = atomicAdd(&g_barcnt, 1u);
                        if (old == gridDim.x - 1) {
                            g_barcnt = 0;
                            __threadfence();
                            atomicAdd(&g_bargen, 1u);
                        } else {
                            while (atomicAdd(&g_bargen, 0u) == g) __nanosleep(64);
                        }
                        __threadfence();
                    }
                    BAR_SYNC(GBARS, NST);
                }
                const uint32_t* hcur = g_hPack[t & 1];
                for (int ch = 0; ch < nch; ch++) {
                    int s = cnt & 1;
                    if (cnt >= 2) BAR_SYNC(EMPT0 + s, NT);
                    const int k0 = ch << 6;
                    uint4 vv[6];
#pragma unroll
                    for (int j = 0; j < 6; j++) {
                        int idx = stid + j * NST;
                        uint4 v = make_uint4(0, 0, 0, 0);
                        if (idx < 1600) {
                            int r = idx >> 4, q = idx & 15;
                            int m = grp * 100 + r;
                            int kg = k0 + q * 4;
                            if (kg < HID)
                                v = __ldcg((const uint4*)(hcur + m * HID + kg));
                            else if (kg + 4 <= Ktot)
                                v = __ldcg((const uint4*)(xsrc + (long)m * xrs + (long)t * xw + (kg - HID)));
                        }
                        vv[j] = v;
                    }
                    const uint4* wsrc = (const uint4*)(g_wlo + (size_t)(bid * 24 + ch) * 3072);
                    uint4 wl0 = __ldcg(wsrc + stid);
                    uint4 wl1;
                    bool w1v = (stid + NST) < 384;
                    if (w1v) wl1 = __ldcg(wsrc + stid + NST);

                    char* ab = smc + OFF_A + s * 28672;
#pragma unroll
                    for (int j = 0; j < 6; j++) {
                        int idx = stid + j * NST;
                        if (idx < 1600) {
                            int r = idx >> 4, q = idx & 15;
                            uint4 v = vv[j];
                            uint32_t h01 = __byte_perm(v.x, v.y, 0x5410);
                            uint32_t h23 = __byte_perm(v.z, v.w, 0x5410);
                            uint32_t l01 = __byte_perm(v.x, v.y, 0x7632);
                            uint32_t l23 = __byte_perm(v.z, v.w, 0x7632);
                            unsigned off = sw128((unsigned)(r * 128 + q * 8));
                            *(uint2*)(ab + off) = make_uint2(h01, h23);
                            *(uint2*)(ab + 14336 + off) = make_uint2(l01, l23);
                        }
                    }
                    *((uint4*)(smc + OFF_BL + s * 6144) + stid) = wl0;
                    if (w1v) *((uint4*)(smc + OFF_BL + s * 6144) + stid + NST) = wl1;
                    __threadfence_block();
                    BAR_ARRIVE(FULL0 + s, NT);
                    cnt++;
                }
            }
        } else {
            // =============== COMPUTE warps (7): MMA + epilogue ===============
            float creg[6];
#pragma unroll
            for (int i = 0; i < 6; i++) creg[i] = 0.f;
            const int gL = lane & 3;
            const int rLo = lane >> 2;
            const bool evenL = ((gL & 1) == 0);

            for (int t = 0; t < WINL; t++) {
                uint32_t* hnxt = g_hPack[(t + 1) & 1];

                float acc[6][4];
#pragma unroll
                for (int nt = 0; nt < 6; nt++) {
                    float bA = b_s[8 * nt + 2 * gL];
                    float bB = b_s[8 * nt + 2 * gL + 1];
                    acc[nt][0] = bA; acc[nt][1] = bB;
                    acc[nt][2] = bA; acc[nt][3] = bB;
                }

                for (int ch = 0; ch < nch; ch++) {
                    int s = cnt & 1;
                    BAR_SYNC(FULL0 + s, NT);
                    const uint32_t aB  = sb + OFF_A + (uint32_t)s * 28672u;
                    const uint32_t blB = sb + OFF_BL + (uint32_t)s * 6144u;
                    const uint32_t bhB = sb + OFF_BH + (uint32_t)ch * 6144u;

                    // double-buffered fragment sets, software-pipelined over ks
                    uint32_t ah[2][4], al[2][4], bh[2][3][4], bl[2][3][4];
                    {   // preload ks = 0 into set 0
                        uint32_t ao = aBB ^ aSwz;
                        ldsm4(ah[0], aB + ao);
                        ldsm4(al[0], aB + 14336u + ao);
#pragma unroll
                        for (int g = 0; g < 3; g++) {
                            uint32_t bo = (((uint32_t)(g * 16) + colRel) * 128u + bKofs) ^ bSwzL;
                            ldsm4(bh[0][g], bhB + bo);
                            ldsm4(bl[0][g], blB + bo);
                        }
                    }
#pragma unroll
                    for (int ks = 0; ks < 4; ks++) {
                        const int cur = ks & 1, nxt = cur ^ 1;
                        if (ks < 3) {   // prefetch next k16 fragments
                            uint32_t ao = (aBB + (uint32_t)(ks + 1) * 32u) ^ aSwz;
                            ldsm4(ah[nxt], aB + ao);
                            ldsm4(al[nxt], aB + 14336u + ao);
#pragma unroll
                            for (int g = 0; g < 3; g++) {
                                uint32_t bo = (((uint32_t)(g * 16) + colRel) * 128u + bKofs
                                               + (uint32_t)(ks + 1) * 32u) ^ bSwzL;
                                ldsm4(bh[nxt][g], bhB + bo);
                                ldsm4(bl[nxt][g], blB + bo);
                            }
                        }
                        if (ks == 2) BAR_ARRIVE(EMPT0 + s, NT);  // all smem reads for this chunk done

                        // pass 1: ah*bh  (6 independent accumulators)
                        mma16816(acc[0], ah[cur], bh[cur][0]);
                        mma16816(acc[2], ah[cur], bh[cur][1]);
                        mma16816(acc[4], ah[cur], bh[cur][2]);
                        mma16816(acc[1], ah[cur], bh[cur][0] + 2);
                        mma16816(acc[3], ah[cur], bh[cur][1] + 2);
                        mma16816(acc[5], ah[cur], bh[cur][2] + 2);
                        // pass 2: al*bh
                        mma16816(acc[0], al[cur], bh[cur][0]);
                        mma16816(acc[2], al[cur], bh[cur][1]);
                        mma16816(acc[4], al[cur], bh[cur][2]);
                        mma16816(acc[1], al[cur], bh[cur][0] + 2);
                        mma16816(acc[3], al[cur], bh[cur][1] + 2);
                        mma16816(acc[5], al[cur], bh[cur][2] + 2);
                        // pass 3: ah*bl
                        mma16816(acc[0], ah[cur], bl[cur][0]);
                        mma16816(acc[2], ah[cur], bl[cur][1]);
                        mma16816(acc[4], ah[cur], bl[cur][2]);
                        mma16816(acc[1], ah[cur], bl[cur][0] + 2);
                        mma16816(acc[3], ah[cur], bl[cur][1] + 2);
                        mma16816(acc[5], ah[cur], bl[cur][2] + 2);
                    }
                    cnt++;
                }

                // ---- epilogue: lane exchange + cell update, all in registers ----
#pragma unroll
                for (int nt = 0; nt < 6; nt++) {
                    float o0 = __shfl_xor_sync(0xffffffffu, acc[nt][0], 1);
                    float o1 = __shfl_xor_sync(0xffffffffu, acc[nt][1], 1);
                    float o2 = __shfl_xor_sync(0xffffffffu, acc[nt][2], 1);
                    float o3 = __shfl_xor_sync(0xffffffffu, acc[nt][3], 1);
                    float gi, gf, gg, go;
                    int row;
                    if (evenL) { gi = acc[nt][0]; gf = acc[nt][1]; gg = o0; go = o1; row = rLo; }
                    else       { gi = o2; gf = o3; gg = acc[nt][2]; go = acc[nt][3]; row = rLo + 8; }
                    float c = creg[nt];
                    c = sigf(gf) * c + sigf(gi) * tanhfast(gg);
                    float h = sigf(go) * tanhfast(c);
                    creg[nt] = c;
                    int mrow = wid * 16 + row;
                    if (mrow < 100) {
                        int u = 2 * nt + (gL >> 1);
                        int m = grp * 100 + mrow;
                        uint32_t pk = packf(h);
                        hnxt[m * HID + u0 + u] = pk;
                        if (seqOut) seqOut[(size_t)(m * WINL + t) * HID + u0 + u] = pk;
                        else if (t == WINL - 1) g_hF[m * HID + u0 + u] = h;
                    }
                }
                __threadfence();
                if (t != WINL - 1) BAR_ARRIVE(HDONE, NT);
#pragma unroll
                for (int i = 0; i < 6; i++) if (t == WINL - 1) creg[i] = 0.f;
            }
        }
        // layer boundary: both groups fall through; next grid_bar in prep syncs everyone
    }
}

// ---------------- output projection + row normalize ----------------
__global__ void out_proj_kernel(const float* __restrict__ w_out,
                                const float* __restrict__ b_out)
{
    __shared__ float red[256];
    int b = blockIdx.x;
    int o = threadIdx.x;
    const float4* h = (const float4*)(g_hF + (long)b * HID);
    const float4* w = (const float4*)(w_out + (long)o * HID);
    float s = 0.f;
#pragma unroll 4
    for (int k = 0; k < HID / 4; k++) {
        float4 hv = h[k];
        float4 wv = w[k];
        s += hv.x * wv.x + hv.y * wv.y + hv.z * wv.z + hv.w * wv.w;
    }
    float y = s + b_out[o];
    red[o] = y * y;
    __syncthreads();
    for (int st = 128; st > 0; st >>= 1) {
        if (o < st) red[o] += red[o + st];
        __syncthreads();
    }
    float inv = rsqrtf(red[0]);
    g_y[b * 256 + o] = y * inv;
}

__global__ void mean_kernel(float* __restrict__ out) {
    int o = threadIdx.x;
    float s = 0.f;
    for (int b = 0; b < NWIN; b++) s += g_y[b * 256 + o];
    out[o] = s / (float)NWIN;
}

// ---------------- launch ----------------
extern "C" void kernel_launch(void* const* d_in, const int* in_sizes, int n_in,
                              void* d_out, int out_size)
{
    (void)in_sizes; (void)n_in; (void)out_size;
    P p;
    p.x    = (const float*)d_in[0];
    p.wih0 = (const float*)d_in[1];  p.whh0 = (const float*)d_in[2];
    p.bih0 = (const float*)d_in[3];  p.bhh0 = (const float*)d_in[4];
    p.wih1 = (const float*)d_in[5];  p.whh1 = (const float*)d_in[6];
    p.bih1 = (const float*)d_in[7];  p.bhh1 = (const float*)d_in[8];
    p.wih2 = (const float*)d_in[9];  p.whh2 = (const float*)d_in[10];
    p.bih2 = (const float*)d_in[11]; p.bhh2 = (const float*)d_in[12];
    const float* w_out = (const float*)d_in[13];
    const float* b_out = (const float*)d_in[14];
    float* out = (float*)d_out;

    cudaFuncSetAttribute(lstm_all, cudaFuncAttributeMaxDynamicSharedMemorySize, SMEM_TOT);

    lstm_all<<<NB, NT, SMEM_TOT>>>(p);
    out_proj_kernel<<<NWIN, 256>>>(w_out, b_out);
    mean_kernel<<<1, 256>>>(out);
}

// round 17
// speedup vs baseline: 1.1958x; 1.1958x over previous
#include <cuda_runtime.h>
#include <cuda_bf16.h>
#include <math.h>
#include <stdint.h>

// ---------------- problem constants ----------------
#define NWIN 200
#define WINL 160
#define HOPL 80
#define INPD 40
#define HID  768
#define NB   128
#define NT   512
#define NCT  224           // compute threads (7 warps)
#define NST  288           // staging threads (9 warps)
#define NHCH 12            // h chunks (768/64)

// smem layout (bytes)
#define OFF_BS   0                   // bias: 48 floats
#define OFF_A    1024                // A ring: 2 slots x (hi 14336 + lo 14336) = 57344
#define OFF_BL   58368               // Wlo ring: 2 slots x 6144
#define OFF_BH   70656               // Wh resident: 24 chunks x 48 rows x 128B = 147456
#define SMEM_TOT 218112

// named barrier ids (0 reserved for __syncthreads)
#define FULL0 1
#define FULL1 2
#define EMPT0 3
#define EMPT1 4
#define HDONE 5
#define GBARS 6

#define BAR_SYNC(id, cnt)   asm volatile("bar.sync %0, %1;"   :: "r"(id), "r"(cnt) : "memory")
#define BAR_ARRIVE(id, cnt) asm volatile("bar.arrive %0, %1;" :: "r"(id), "r"(cnt) : "memory")

// ---------------- persistent device scratch ----------------
__device__ uint32_t g_hPack[2][NWIN * HID];            // packed (lo16<<16 | hi16) bf16 pairs
__device__ uint32_t g_seqPack[2][NWIN * WINL * HID];   // layer0/1 output sequences
__device__ uint32_t g_xPack[NWIN * WINL * INPD + 64];  // windowed input, packed
__device__ __align__(16) __nv_bfloat16 g_wlo[NB * 24 * 3072];  // per-CTA pre-swizzled Wlo
__device__ float g_hF[NWIN * HID];                     // final-layer h (fp32)
__device__ float g_y[NWIN * 256];
__device__ unsigned g_cnt8[8];                         // 2-level grid barrier
__device__ unsigned g_root = 0;
__device__ unsigned g_gen = 0;

struct P {
    const float *x;
    const float *wih0, *whh0, *bih0, *bhh0;
    const float *wih1, *whh1, *bih1, *bhh1;
    const float *wih2, *whh2, *bih2, *bhh2;
};

// ---------------- helpers ----------------
__device__ __forceinline__ uint32_t smem_u32(const void* p) {
    uint32_t a;
    asm("{ .reg .u64 t; cvta.to.shared.u64 t, %1; cvt.u32.u64 %0, t; }" : "=r"(a) : "l"(p));
    return a;
}
// 2-level inter-CTA barrier, called by ONE thread per CTA
__device__ __forceinline__ void ctabar_one(int bid) {
    unsigned g = __ldcg(&g_gen);          // gen only changes at release
    __threadfence();                      // release my prior writes
    int gi = bid >> 4;                    // 8 groups of 16 CTAs
    if (atomicAdd(&g_cnt8[gi], 1u) == 15u) {
        if (atomicAdd(&g_root, 1u) == 7u) {
            g_root = 0;
#pragma unroll
            for (int i = 0; i < 8; i++) g_cnt8[i] = 0;
            __threadfence();
            atomicAdd(&g_gen, 1u);
        }
    }
    while (__ldcg(&g_gen) == g) __nanosleep(64);
    __threadfence();                      // acquire others' writes
}
__device__ __forceinline__ void grid_bar() {           // all-thread barrier (prep only)
    __syncthreads();
    if (threadIdx.x == 0) ctabar_one(blockIdx.x);
    __syncthreads();
}
__device__ __forceinline__ float sigf(float v) { return 1.f / (1.f + __expf(-v)); }
__device__ __forceinline__ float tanhfast(float x) {
    float ax = fabsf(x);
    float e = __expf(-2.f * ax);
    return copysignf((1.f - e) / (1.f + e), x);
}
__device__ __forceinline__ unsigned sw128(unsigned off) { return off ^ ((off >> 3) & 0x70); }
__device__ __forceinline__ uint32_t packf(float v) {
    __nv_bfloat16 h = __float2bfloat16(v);
    __nv_bfloat16 l = __float2bfloat16(v - __bfloat162float(h));
    return ((uint32_t)__bfloat16_as_ushort(l) << 16) | (uint32_t)__bfloat16_as_ushort(h);
}
__device__ __forceinline__ void mma16816(float* d, const uint32_t* a, const uint32_t* b) {
    asm volatile(
        "mma.sync.aligned.m16n8k16.row.col.f32.bf16.bf16.f32 "
        "{%0,%1,%2,%3}, {%4,%5,%6,%7}, {%8,%9}, {%0,%1,%2,%3};"
        : "+f"(d[0]), "+f"(d[1]), "+f"(d[2]), "+f"(d[3])
        : "r"(a[0]), "r"(a[1]), "r"(a[2]), "r"(a[3]), "r"(b[0]), "r"(b[1]));
}
__device__ __forceinline__ void ldsm4(uint32_t* r, uint32_t addr) {
    asm volatile("ldmatrix.sync.aligned.m8n8.x4.shared.b16 {%0,%1,%2,%3}, [%4];"
        : "=r"(r[0]), "=r"(r[1]), "=r"(r[2]), "=r"(r[3]) : "r"(addr));
}

// ============================================================
// Persistent kernel: full 3-layer, 160-step LSTM recurrence
// ============================================================
__global__ void __launch_bounds__(NT, 1) lstm_all(P p)
{
    extern __shared__ char smc[];
    const uint32_t sb = smem_u32(smc);
    float* b_s = (float*)(smc + OFF_BS);

    const int tid  = threadIdx.x;
    const int wid  = tid >> 5;
    const int lane = tid & 31;
    const int bid  = blockIdx.x;
    const int grp  = bid >> 6;               // rows grp*100 .. +99
    const int nb   = bid & 63;
    const int u0   = nb * 12;                // 12 hidden units owned
    const bool isC = (tid < NCT);            // compute warps 0-6
    const int stid = tid - NCT;              // staging thread id (valid if !isC)

    // compute-warp ldmatrix geometry (m-tile = wid; B spans all 48 cols)
    const int aRow = wid * 16 + (lane & 15);
    const uint32_t aSwz = (uint32_t)(aRow & 7) << 4;
    const uint32_t aBB  = (uint32_t)aRow * 128 + ((lane & 16) ? 16u : 0u);
    const uint32_t colRel = (uint32_t)((lane & 7) + ((lane & 16) ? 8 : 0));
    const uint32_t bSwzL  = (uint32_t)(lane & 7) << 4;
    const uint32_t bKofs  = (lane & 8) ? 16u : 0u;

    // zero the whole A ring once: pad rows (100..111) stay zero forever
    for (int i = tid * 16; i < 57344; i += NT * 16)
        *(uint4*)(smc + OFF_A + i) = make_uint4(0, 0, 0, 0);

    // precompute windowed, packed input (whole grid)
    for (int idx = bid * NT + tid; idx < NWIN * WINL * INPD; idx += NB * NT) {
        int m = idx / (WINL * INPD);
        int r2 = idx - m * WINL * INPD;
        int tt = r2 / INPD;
        int i = r2 - tt * INPD;
        g_xPack[idx] = packf(__ldcg(&p.x[(m * HOPL + tt) * INPD + i]));
    }
    grid_bar();

    const float* wihA[3] = { p.wih0, p.wih1, p.wih2 };
    const float* whhA[3] = { p.whh0, p.whh1, p.whh2 };
    const float* bihA[3] = { p.bih0, p.bih1, p.bih2 };
    const float* bhhA[3] = { p.bhh0, p.bhh1, p.bhh2 };

    unsigned cnt = 0;                         // chunk ring cursor (both groups track)

    for (int l = 0; l < 3; l++) {
        const int in_dim = (l == 0) ? INPD : HID;
        const int Ktot = HID + in_dim;
        const int nch = (Ktot + 63) >> 6;     // 13 or 24
        const int nx  = nch - NHCH;           // x chunks: 1 or 12
        const uint32_t* xsrc = (l == 0) ? g_xPack : g_seqPack[l - 1];
        const long xrs = (l == 0) ? (long)WINL * INPD : (long)WINL * HID;
        const int xw = (l == 0) ? INPD : HID;
        uint32_t* seqOut = (l < 2) ? g_seqPack[l] : nullptr;
        const float* wih = wihA[l];
        const float* whh = whhA[l];

        // ---- weight prep (all threads): Wh hi -> smem resident, Wlo -> pre-swizzled global ----
        for (int idx = tid; idx < 48 * 1536; idx += NT) {
            int j = idx / 1536, k = idx - j * 1536;
            int u = j >> 2, g = j & 3;
            int col = g * HID + u0 + u;
            float v = 0.f;
            if (k < HID) v = whh[col * HID + k];
            else { int kk = k - HID; if (kk < in_dim) v = wih[col * in_dim + kk]; }
            __nv_bfloat16 hi = __float2bfloat16(v);
            __nv_bfloat16 lo = __float2bfloat16(v - __bfloat162float(hi));
            int ch = k >> 6, kk2 = k & 63;
            unsigned sw = sw128((unsigned)(j * 128 + kk2 * 2));
            *(__nv_bfloat16*)(smc + OFF_BH + ch * 6144 + sw) = hi;
            g_wlo[(size_t)(bid * 24 + ch) * 3072 + (sw >> 1)] = lo;
        }
        if (tid < 48) {
            int u = tid >> 2, g = tid & 3;
            int col = g * HID + u0 + u;
            b_s[tid] = bihA[l][col] + bhhA[l][col];
        }
        for (int i = tid; i < 1200; i += NT) g_hPack[0][bid * 1200 + i] = 0u;
        grid_bar();

        if (!isC) {
            // =============== PRODUCER warps (9): stage A + Wlo chunks ===============
            // chunk order per step: x chunks (no h dependency) FIRST, then h chunks.
            // The inter-CTA h barrier sits between them, hidden under x compute.
            for (int t = 0; t < WINL; t++) {
                const uint32_t* hcur = g_hPack[t & 1];
                for (int i = 0; i < nch; i++) {
                    if (i == nx && t > 0) {
                        BAR_SYNC(HDONE, NT);             // local epilogue of t-1 done
                        if (stid == 0) ctabar_one(bid);  // all CTAs' h(t) visible
                        BAR_SYNC(GBARS, NST);
                    }
                    const int ch = (i < nx) ? (NHCH + i) : (i - nx);
                    int s = cnt & 1;
                    if (cnt >= 2) BAR_SYNC(EMPT0 + s, NT);
                    const int k0 = ch << 6;
                    uint4 vv[6];
#pragma unroll
                    for (int j = 0; j < 6; j++) {
                        int idx = stid + j * NST;
                        uint4 v = make_uint4(0, 0, 0, 0);
                        if (idx < 1600) {
                            int r = idx >> 4, q = idx & 15;
                            int m = grp * 100 + r;
                            int kg = k0 + q * 4;
                            if (kg < HID)
                                v = __ldcg((const uint4*)(hcur + m * HID + kg));
                            else if (kg + 4 <= Ktot)
                                v = __ldcg((const uint4*)(xsrc + (long)m * xrs + (long)t * xw + (kg - HID)));
                        }
                        vv[j] = v;
                    }
                    const uint4* wsrc = (const uint4*)(g_wlo + (size_t)(bid * 24 + ch) * 3072);
                    uint4 wl0 = __ldcg(wsrc + stid);
                    uint4 wl1;
                    bool w1v = (stid + NST) < 384;
                    if (w1v) wl1 = __ldcg(wsrc + stid + NST);

                    char* ab = smc + OFF_A + s * 28672;
#pragma unroll
                    for (int j = 0; j < 6; j++) {
                        int idx = stid + j * NST;
                        if (idx < 1600) {
                            int r = idx >> 4, q = idx & 15;
                            uint4 v = vv[j];
                            uint32_t h01 = __byte_perm(v.x, v.y, 0x5410);
                            uint32_t h23 = __byte_perm(v.z, v.w, 0x5410);
                            uint32_t l01 = __byte_perm(v.x, v.y, 0x7632);
                            uint32_t l23 = __byte_perm(v.z, v.w, 0x7632);
                            unsigned off = sw128((unsigned)(r * 128 + q * 8));
                            *(uint2*)(ab + off) = make_uint2(h01, h23);
                            *(uint2*)(ab + 14336 + off) = make_uint2(l01, l23);
                        }
                    }
                    *((uint4*)(smc + OFF_BL + s * 6144) + stid) = wl0;
                    if (w1v) *((uint4*)(smc + OFF_BL + s * 6144) + stid + NST) = wl1;
                    __threadfence_block();
                    BAR_ARRIVE(FULL0 + s, NT);
                    cnt++;
                }
            }
        } else {
            // =============== COMPUTE warps (7): MMA + epilogue ===============
            float creg[6];
#pragma unroll
            for (int i = 0; i < 6; i++) creg[i] = 0.f;
            const int gL = lane & 3;
            const int rLo = lane >> 2;
            const bool evenL = ((gL & 1) == 0);

            for (int t = 0; t < WINL; t++) {
                uint32_t* hnxt = g_hPack[(t + 1) & 1];

                float acc[6][4];
#pragma unroll
                for (int nt = 0; nt < 6; nt++) {
                    float bA = b_s[8 * nt + 2 * gL];
                    float bB = b_s[8 * nt + 2 * gL + 1];
                    acc[nt][0] = bA; acc[nt][1] = bB;
                    acc[nt][2] = bA; acc[nt][3] = bB;
                }

                for (int i = 0; i < nch; i++) {
                    const int ch = (i < nx) ? (NHCH + i) : (i - nx);
                    int s = cnt & 1;
                    BAR_SYNC(FULL0 + s, NT);
                    const uint32_t aB  = sb + OFF_A + (uint32_t)s * 28672u;
                    const uint32_t blB = sb + OFF_BL + (uint32_t)s * 6144u;
                    const uint32_t bhB = sb + OFF_BH + (uint32_t)ch * 6144u;
#pragma unroll
                    for (int ks = 0; ks < 4; ks++) {
                        uint32_t ah[4], al[4], bh[3][4], bl[3][4];
                        uint32_t ao = (aBB + (uint32_t)ks * 32u) ^ aSwz;
                        ldsm4(ah, aB + ao);
                        ldsm4(al, aB + 14336u + ao);
#pragma unroll
                        for (int g = 0; g < 3; g++) {
                            uint32_t bo = (((uint32_t)(g * 16) + colRel) * 128u + bKofs
                                           + (uint32_t)ks * 32u) ^ bSwzL;
                            ldsm4(bh[g], bhB + bo);
                            ldsm4(bl[g], blB + bo);
                        }
                        if (ks == 3) BAR_ARRIVE(EMPT0 + s, NT);  // all smem reads done

                        // pass 1: ah*bh (6 independent accumulators)
                        mma16816(acc[0], ah, bh[0]);
                        mma16816(acc[2], ah, bh[1]);
                        mma16816(acc[4], ah, bh[2]);
                        mma16816(acc[1], ah, bh[0] + 2);
                        mma16816(acc[3], ah, bh[1] + 2);
                        mma16816(acc[5], ah, bh[2] + 2);
                        // pass 2: al*bh
                        mma16816(acc[0], al, bh[0]);
                        mma16816(acc[2], al, bh[1]);
                        mma16816(acc[4], al, bh[2]);
                        mma16816(acc[1], al, bh[0] + 2);
                        mma16816(acc[3], al, bh[1] + 2);
                        mma16816(acc[5], al, bh[2] + 2);
                        // pass 3: ah*bl
                        mma16816(acc[0], ah, bl[0]);
                        mma16816(acc[2], ah, bl[1]);
                        mma16816(acc[4], ah, bl[2]);
                        mma16816(acc[1], ah, bl[0] + 2);
                        mma16816(acc[3], ah, bl[1] + 2);
                        mma16816(acc[5], ah, bl[2] + 2);
                    }
                    cnt++;
                }

                // ---- epilogue: lane exchange + cell update, all in registers ----
#pragma unroll
                for (int nt = 0; nt < 6; nt++) {
                    float o0 = __shfl_xor_sync(0xffffffffu, acc[nt][0], 1);
                    float o1 = __shfl_xor_sync(0xffffffffu, acc[nt][1], 1);
                    float o2 = __shfl_xor_sync(0xffffffffu, acc[nt][2], 1);
                    float o3 = __shfl_xor_sync(0xffffffffu, acc[nt][3], 1);
                    float gi, gf, gg, go;
                    int row;
                    if (evenL) { gi = acc[nt][0]; gf = acc[nt][1]; gg = o0; go = o1; row = rLo; }
                    else       { gi = o2; gf = o3; gg = acc[nt][2]; go = acc[nt][3]; row = rLo + 8; }
                    float c = creg[nt];
                    c = sigf(gf) * c + sigf(gi) * tanhfast(gg);
                    float h = sigf(go) * tanhfast(c);
                    creg[nt] = c;
                    int mrow = wid * 16 + row;
                    if (mrow < 100) {
                        int u = 2 * nt + (gL >> 1);
                        int m = grp * 100 + mrow;
                        uint32_t pk = packf(h);
                        hnxt[m * HID + u0 + u] = pk;
                        if (seqOut) seqOut[(size_t)(m * WINL + t) * HID + u0 + u] = pk;
                        else if (t == WINL - 1) g_hF[m * HID + u0 + u] = h;
                    }
                }
                __threadfence();
                if (t != WINL - 1) BAR_ARRIVE(HDONE, NT);
                if (t == WINL - 1) {
#pragma unroll
                    for (int i = 0; i < 6; i++) creg[i] = 0.f;
                }
            }
        }
        // layer boundary: both groups fall through; prep grid_bar syncs everyone
    }
}

// ---------------- output projection + row normalize ----------------
__global__ void out_proj_kernel(const float* __restrict__ w_out,
                                const float* __restrict__ b_out)
{
    __shared__ float red[256];
    int b = blockIdx.x;
    int o = threadIdx.x;
    const float4* h = (const float4*)(g_hF + (long)b * HID);
    const float4* w = (const float4*)(w_out + (long)o * HID);
    float s = 0.f;
#pragma unroll 4
    for (int k = 0; k < HID / 4; k++) {
        float4 hv = h[k];
        float4 wv = w[k];
        s += hv.x * wv.x + hv.y * wv.y + hv.z * wv.z + hv.w * wv.w;
    }
    float y = s + b_out[o];
    red[o] = y * y;
    __syncthreads();
    for (int st = 128; st > 0; st >>= 1) {
        if (o < st) red[o] += red[o + st];
        __syncthreads();
    }
    float inv = rsqrtf(red[0]);
    g_y[b * 256 + o] = y * inv;
}

__global__ void mean_kernel(float* __restrict__ out) {
    int o = threadIdx.x;
    float s = 0.f;
    for (int b = 0; b < NWIN; b++) s += g_y[b * 256 + o];
    out[o] = s / (float)NWIN;
}

// ---------------- launch ----------------
extern "C" void kernel_launch(void* const* d_in, const int* in_sizes, int n_in,
                              void* d_out, int out_size)
{
    (void)in_sizes; (void)n_in; (void)out_size;
    P p;
    p.x    = (const float*)d_in[0];
    p.wih0 = (const float*)d_in[1];  p.whh0 = (const float*)d_in[2];
    p.bih0 = (const float*)d_in[3];  p.bhh0 = (const float*)d_in[4];
    p.wih1 = (const float*)d_in[5];  p.whh1 = (const float*)d_in[6];
    p.bih1 = (const float*)d_in[7];  p.bhh1 = (const float*)d_in[8];
    p.wih2 = (const float*)d_in[9];  p.whh2 = (const float*)d_in[10];
    p.bih2 = (const float*)d_in[11]; p.bhh2 = (const float*)d_in[12];
    const float* w_out = (const float*)d_in[13];
    const float* b_out = (const float*)d_in[14];
    float* out = (float*)d_out;

    cudaFuncSetAttribute(lstm_all, cudaFuncAttributeMaxDynamicSharedMemorySize, SMEM_TOT);

    lstm_all<<<NB, NT, SMEM_TOT>>>(p);
    out_proj_kernel<<<NWIN, 256>>>(w_out, b_out);
    mean_kernel<<<1, 256>>>(out);
}